// round 7
// baseline (speedup 1.0000x reference)
#include <cuda_runtime.h>
#include <cuda_bf16.h>
#include <math.h>
#include <stdint.h>

#define Nn   4
#define CIN  1024
#define CB   256
#define Hh   56
#define Ww   56
#define HW   3136
#define KT   9
#define KD   (CB * KT)   // 2304

// Scratch (device globals: allocation-free rule)
__device__ float g_r  [Nn * CB * HW];     // conv1 output (relu)
__device__ float g_off[Nn * 2 * KT * HW]; // offset conv output
__device__ float g_r2 [Nn * CB * HW];     // deform conv output (relu)
__device__ __nv_bfloat16 g_w2h[CB * KD];  // w2 split hi, [o][tap*256+c]
__device__ __nv_bfloat16 g_w2l[CB * KD];  // w2 split lo

// ---------------------------------------------------------------------------
// helpers
// ---------------------------------------------------------------------------
__device__ __forceinline__ void split2(float x, float y, uint32_t& hi, uint32_t& lo) {
    __nv_bfloat16 xh = __float2bfloat16(x);
    __nv_bfloat16 yh = __float2bfloat16(y);
    __nv_bfloat16 xl = __float2bfloat16(x - __bfloat162float(xh));
    __nv_bfloat16 yl = __float2bfloat16(y - __bfloat162float(yh));
    hi = ((uint32_t)__bfloat16_as_ushort(yh) << 16) | __bfloat16_as_ushort(xh);
    lo = ((uint32_t)__bfloat16_as_ushort(yl) << 16) | __bfloat16_as_ushort(xl);
}
__device__ __forceinline__ void split8(const float4& a, const float4& b,
                                       uint4& hi, uint4& lo) {
    split2(a.x, a.y, hi.x, lo.x);
    split2(a.z, a.w, hi.y, lo.y);
    split2(b.x, b.y, hi.z, lo.z);
    split2(b.z, b.w, hi.w, lo.w);
}

__device__ __forceinline__ void mma16816(float* c, const uint32_t* a, const uint32_t* b) {
    asm volatile(
        "mma.sync.aligned.m16n8k16.row.col.f32.bf16.bf16.f32 "
        "{%0,%1,%2,%3}, {%4,%5,%6,%7}, {%8,%9}, {%0,%1,%2,%3};"
        : "+f"(c[0]), "+f"(c[1]), "+f"(c[2]), "+f"(c[3])
        : "r"(a[0]), "r"(a[1]), "r"(a[2]), "r"(a[3]), "r"(b[0]), "r"(b[1]));
}

__device__ __forceinline__ void ldsm_x4(uint32_t* r, uint32_t addr) {
    asm volatile("ldmatrix.sync.aligned.m8n8.x4.shared.b16 {%0,%1,%2,%3}, [%4];"
                 : "=r"(r[0]), "=r"(r[1]), "=r"(r[2]), "=r"(r[3]) : "r"(addr));
}
__device__ __forceinline__ void ldsm_x2(uint32_t* r, uint32_t addr) {
    asm volatile("ldmatrix.sync.aligned.m8n8.x2.shared.b16 {%0,%1}, [%2];"
                 : "=r"(r[0]), "=r"(r[1]) : "r"(addr));
}
template <int P>
__device__ __forceinline__ uint32_t a_addr(const __nv_bfloat16 (*S)[P], int mb, int ks, int ln) {
    int row = mb + (ln & 7) + ((ln >> 3) & 1) * 8;
    int col = ks + (ln >> 4) * 8;
    return (uint32_t)__cvta_generic_to_shared(&S[row][col]);
}
template <int P>
__device__ __forceinline__ uint32_t b_addr(const __nv_bfloat16 (*S)[P], int nb, int ks, int ln) {
    int l = ln & 15;
    int row = nb + (l & 7);
    int col = ks + ((l >> 3) & 1) * 8;
    return (uint32_t)__cvta_generic_to_shared(&S[row][col]);
}
__device__ __forceinline__ void cp16(uint32_t saddr, const void* g) {
    asm volatile("cp.async.ca.shared.global [%0], [%1], 16;"
                 :: "r"(saddr), "l"(g) : "memory");
}
#define CP_COMMIT() asm volatile("cp.async.commit_group;" ::: "memory")
#define CP_WAIT0()  asm volatile("cp.async.wait_group 0;" ::: "memory")
#define CP_WAIT1()  asm volatile("cp.async.wait_group 1;" ::: "memory")

// ---------------------------------------------------------------------------
// w2 (o,c,kh,kw) fp32 -> bf16 hi/lo at [o][tap*256+c]
// ---------------------------------------------------------------------------
__global__ void prep_w2_kernel(const float* __restrict__ w2) {
    int i = blockIdx.x * 256 + threadIdx.x;
    if (i < CB * KD) {
        int o = i / KD;
        int k = i % KD;
        int tap = k >> 8;
        int c   = k & 255;
        float v = w2[(o * CB + c) * KT + tap];
        __nv_bfloat16 h = __float2bfloat16(v);
        g_w2h[i] = h;
        g_w2l[i] = __float2bfloat16(v - __bfloat162float(h));
    }
}

// ===========================================================================
// Tensor-core (HMMA) GEMM for the 1x1 convs (unchanged from R6).
// ===========================================================================
#define BKP 40

__global__ __launch_bounds__(256) void gemm_tc_kernel(
        const float* __restrict__ A, const float* __restrict__ Bx,
        const float* __restrict__ bias, const float* __restrict__ resid,
        float* __restrict__ C, int M, int Kd) {
    __shared__ __nv_bfloat16 As_hi[128][BKP];
    __shared__ __nv_bfloat16 As_lo[128][BKP];
    __shared__ __nv_bfloat16 Bs_hi[64][BKP];
    __shared__ __nv_bfloat16 Bs_lo[64][BKP];

    const int n  = blockIdx.z;
    const int m0 = blockIdx.y * 128;
    const int p0 = blockIdx.x * 64;
    const int tid = threadIdx.x;
    const int wid = tid >> 5;
    const int lid = tid & 31;
    const int q = lid >> 2;
    const int r = lid & 3;
    const int warp_m = wid >> 2;
    const int warp_n = wid & 3;
    const float* Bn = Bx + (size_t)n * Kd * HW;

    const int a_row0 = tid >> 2;
    const int a_kg   = (tid & 3) * 8;
    const int b_k   = (tid & 15) * 2;
    const int b_px  = (tid >> 4) * 4;

    float acc[4][2][4] = {};
    const int KC = Kd >> 5;

    float4 ga[2][2], gb[2];
    {
        const float* g0 = A + (size_t)(m0 + a_row0) * Kd + a_kg;
        ga[0][0] = *(const float4*)g0;
        ga[0][1] = *(const float4*)(g0 + 4);
        const float* g1 = A + (size_t)(m0 + a_row0 + 64) * Kd + a_kg;
        ga[1][0] = *(const float4*)g1;
        ga[1][1] = *(const float4*)(g1 + 4);
        const float* gB = Bn + (size_t)b_k * HW + p0 + b_px;
        gb[0] = *(const float4*)gB;
        gb[1] = *(const float4*)(gB + HW);
    }

    for (int kc = 0; kc < KC; ++kc) {
        __syncthreads();
#pragma unroll
        for (int t = 0; t < 2; ++t) {
            int row = a_row0 + t * 64;
            uint4 hi, lo;
            split8(ga[t][0], ga[t][1], hi, lo);
            *(uint4*)&As_hi[row][a_kg] = hi;
            *(uint4*)&As_lo[row][a_kg] = lo;
        }
        {
            float vk[4]  = {gb[0].x, gb[0].y, gb[0].z, gb[0].w};
            float vk1[4] = {gb[1].x, gb[1].y, gb[1].z, gb[1].w};
#pragma unroll
            for (int j = 0; j < 4; ++j) {
                uint32_t hi, lo;
                split2(vk[j], vk1[j], hi, lo);
                *(uint32_t*)&Bs_hi[b_px + j][b_k] = hi;
                *(uint32_t*)&Bs_lo[b_px + j][b_k] = lo;
            }
        }
        __syncthreads();

        if (kc + 1 < KC) {
            const int k0 = (kc + 1) << 5;
            const float* g0 = A + (size_t)(m0 + a_row0) * Kd + k0 + a_kg;
            ga[0][0] = *(const float4*)g0;
            ga[0][1] = *(const float4*)(g0 + 4);
            const float* g1 = A + (size_t)(m0 + a_row0 + 64) * Kd + k0 + a_kg;
            ga[1][0] = *(const float4*)g1;
            ga[1][1] = *(const float4*)(g1 + 4);
            const float* gB = Bn + (size_t)(k0 + b_k) * HW + p0 + b_px;
            gb[0] = *(const float4*)gB;
            gb[1] = *(const float4*)(gB + HW);
        }

#pragma unroll
        for (int ks = 0; ks < 32; ks += 16) {
            uint32_t bf_hi[2][2], bf_lo[2][2];
#pragma unroll
            for (int nf = 0; nf < 2; ++nf) {
                int nb = warp_n * 16 + nf * 8;
                ldsm_x2(bf_hi[nf], b_addr(Bs_hi, nb, ks, lid));
                ldsm_x2(bf_lo[nf], b_addr(Bs_lo, nb, ks, lid));
            }
#pragma unroll
            for (int mf = 0; mf < 4; ++mf) {
                int mb = warp_m * 64 + mf * 16;
                uint32_t ah[4], al[4];
                ldsm_x4(ah, a_addr(As_hi, mb, ks, lid));
                ldsm_x4(al, a_addr(As_lo, mb, ks, lid));
#pragma unroll
                for (int nf = 0; nf < 2; ++nf) {
                    mma16816(acc[mf][nf], ah, bf_hi[nf]);
                    mma16816(acc[mf][nf], ah, bf_lo[nf]);
                    mma16816(acc[mf][nf], al, bf_hi[nf]);
                }
            }
        }
    }

#pragma unroll
    for (int mf = 0; mf < 4; ++mf) {
#pragma unroll
        for (int nf = 0; nf < 2; ++nf) {
            int m  = m0 + warp_m * 64 + mf * 16 + q;
            int px = p0 + warp_n * 16 + nf * 8 + 2 * r;
#pragma unroll
            for (int half = 0; half < 2; ++half) {
                int mm = m + half * 8;
                float c0 = acc[mf][nf][half * 2 + 0];
                float c1 = acc[mf][nf][half * 2 + 1];
                float bb = bias[mm];
                size_t base = ((size_t)n * M + mm) * HW + px;
                if (resid) {
                    float2 rv = *(const float2*)(resid + base);
                    c0 += rv.x;
                    c1 += rv.y;
                }
                float2 o;
                o.x = fmaxf(c0 + bb, 0.f);
                o.y = fmaxf(c1 + bb, 0.f);
                *(float2*)(C + base) = o;
            }
        }
    }
}

// ---------------------------------------------------------------------------
// Offset conv: 3x3 SAME, CB=256 -> 18 channels (unchanged)
// ---------------------------------------------------------------------------
__global__ void offset_conv_kernel(const float* __restrict__ w_off,
                                   const float* __restrict__ b_off) {
    __shared__ float red[8][64][18];
    const int n  = blockIdx.y;
    const int p0 = blockIdx.x * 64;
    const int tid = threadIdx.x;
    const int g  = tid >> 5;
    const int lx = tid & 31;

    float acc[2][18];
#pragma unroll
    for (int qq = 0; qq < 2; ++qq)
#pragma unroll
        for (int oc = 0; oc < 18; ++oc) acc[qq][oc] = 0.f;

    for (int ci = g; ci < CB; ci += 8) {
        const float* rb = g_r + ((size_t)n * CB + ci) * HW;
        float v[2][9];
#pragma unroll
        for (int qq = 0; qq < 2; ++qq) {
            int p = p0 + lx + qq * 32;
            int h = p / Ww, w = p % Ww;
#pragma unroll
            for (int t = 0; t < 9; ++t) {
                int y = h + t / 3 - 1;
                int x = w + t % 3 - 1;
                v[qq][t] = (y >= 0 && y < Hh && x >= 0 && x < Ww) ? rb[y * Ww + x] : 0.f;
            }
        }
        const float* wb = w_off + ci * 9;
#pragma unroll
        for (int oc = 0; oc < 18; ++oc) {
#pragma unroll
            for (int t = 0; t < 9; ++t) {
                float wv = wb[oc * (CB * 9) + t];
                acc[0][oc] += wv * v[0][t];
                acc[1][oc] += wv * v[1][t];
            }
        }
    }

#pragma unroll
    for (int qq = 0; qq < 2; ++qq)
#pragma unroll
        for (int oc = 0; oc < 18; ++oc)
            red[g][lx + qq * 32][oc] = acc[qq][oc];
    __syncthreads();

    for (int i = tid; i < 64 * 18; i += 256) {
        int ps = i / 18, oc = i % 18;
        float s = b_off[oc];
#pragma unroll
        for (int g2 = 0; g2 < 8; ++g2) s += red[g2][ps][oc];
        g_off[((size_t)n * 18 + oc) * HW + p0 + ps] = s;
    }
}

// ===========================================================================
// Deformable 3x3 conv on tensor cores — double-buffered (2 smem stages):
//  - weights for chunk i+1 staged via cp.async one FULL iteration ahead,
//    so wait_group at consume time is a no-op (off critical path)
//  - gather for chunk i+1 in registers during MMA of chunk i
// k = tap*256 + c; chunks of 64 k; 36 chunks.
// ===========================================================================
#define DPITCH 72
#define STG_BYTES 55296   // per stage: As_h 18432 | As_l 18432 | Bs_h 9216 | Bs_l 9216
#define DSM_BYTES (2 * STG_BYTES)

__global__ __launch_bounds__(256, 2) void deform_mma_kernel(const float* __restrict__ b2) {
    extern __shared__ char dsm[];

    const int pb = blockIdx.x * 64;
    const int m0 = blockIdx.y * 128;
    const int n  = blockIdx.z;
    const int tid = threadIdx.x;
    const int wid = tid >> 5;
    const int lid = tid & 31;
    const int q = lid >> 2;
    const int r = lid & 3;
    const int wm = wid & 3;
    const int wn = wid >> 2;

    const int gpx = tid & 63;
    const int gg  = tid >> 6;
    const int gcl = gg * 16;

    const float* fbase = g_r + (size_t)n * CB * HW;
    const float* offb  = g_off + (size_t)n * 18 * HW + pb + gpx;
    const int gh = (pb + gpx) / Ww;
    const int gw = (pb + gpx) % Ww;

    float acc[2][4][4] = {};

    typedef __nv_bfloat16 (*tile_t)[DPITCH];
#define AS_H(s) ((tile_t)(dsm + (s) * STG_BYTES))
#define AS_L(s) ((tile_t)(dsm + (s) * STG_BYTES + 18432))
#define BS_H(s) ((tile_t)(dsm + (s) * STG_BYTES + 36864))
#define BS_L(s) ((tile_t)(dsm + (s) * STG_BYTES + 46080))

    int   idx0, idx1, idx2, idx3;
    float wt0, wt1, wt2, wt3;
#define BILIN(tap_) do {                                                       \
    float dy = offb[(size_t)((tap_) * 2 + 0) * HW];                            \
    float dx = offb[(size_t)((tap_) * 2 + 1) * HW];                            \
    float ys = (float)(gh + (tap_) / 3 - 1) + dy;                              \
    float xs = (float)(gw + (tap_) % 3 - 1) + dx;                              \
    float y0f = floorf(ys), x0f = floorf(xs);                                  \
    float wy1 = ys - y0f, wy0 = 1.f - wy1;                                     \
    float wx1 = xs - x0f, wx0 = 1.f - wx1;                                     \
    int y0 = (int)y0f, x0 = (int)x0f;                                          \
    int y1 = y0 + 1, x1 = x0 + 1;                                              \
    bool vy0 = (y0 >= 0) && (y0 < Hh);                                         \
    bool vy1 = (y1 >= 0) && (y1 < Hh);                                         \
    bool vx0 = (x0 >= 0) && (x0 < Ww);                                         \
    bool vx1 = (x1 >= 0) && (x1 < Ww);                                         \
    int yc0 = min(max(y0, 0), Hh - 1), yc1 = min(max(y1, 0), Hh - 1);          \
    int xc0 = min(max(x0, 0), Ww - 1), xc1 = min(max(x1, 0), Ww - 1);          \
    idx0 = yc0 * Ww + xc0;  wt0 = (vy0 && vx0) ? wy0 * wx0 : 0.f;              \
    idx1 = yc0 * Ww + xc1;  wt1 = (vy0 && vx1) ? wy0 * wx1 : 0.f;              \
    idx2 = yc1 * Ww + xc0;  wt2 = (vy1 && vx0) ? wy1 * wx0 : 0.f;              \
    idx3 = yc1 * Ww + xc1;  wt3 = (vy1 && vx1) ? wy1 * wx1 : 0.f;              \
} while (0)

    float v[16];
#define GATHER(c0_) do {                                                       \
    _Pragma("unroll")                                                          \
    for (int j = 0; j < 16; ++j) {                                             \
        const float* f = fbase + (size_t)((c0_) + gcl + j) * HW;               \
        v[j] = wt0 * __ldg(f + idx0) + wt1 * __ldg(f + idx1)                   \
             + wt2 * __ldg(f + idx2) + wt3 * __ldg(f + idx3);                  \
    }                                                                          \
} while (0)

#define STORE_B(s_) do {                                                       \
    uint4 h0, h1, l0, l1;                                                      \
    split2(v[0],  v[1],  h0.x, l0.x);                                          \
    split2(v[2],  v[3],  h0.y, l0.y);                                          \
    split2(v[4],  v[5],  h0.z, l0.z);                                          \
    split2(v[6],  v[7],  h0.w, l0.w);                                          \
    split2(v[8],  v[9],  h1.x, l1.x);                                          \
    split2(v[10], v[11], h1.y, l1.y);                                          \
    split2(v[12], v[13], h1.z, l1.z);                                          \
    split2(v[14], v[15], h1.w, l1.w);                                          \
    *(uint4*)&BS_H(s_)[gpx][gcl]     = h0;                                     \
    *(uint4*)&BS_H(s_)[gpx][gcl + 8] = h1;                                     \
    *(uint4*)&BS_L(s_)[gpx][gcl]     = l0;                                     \
    *(uint4*)&BS_L(s_)[gpx][gcl + 8] = l1;                                     \
} while (0)

#define STAGE_W(s_, k0_) do {                                                  \
    tile_t _ah = AS_H(s_);                                                     \
    tile_t _al = AS_L(s_);                                                     \
    _Pragma("unroll")                                                          \
    for (int pass = 0; pass < 4; ++pass) {                                     \
        int id  = tid + pass * 256;                                            \
        int row = id >> 3;                                                     \
        int col = (id & 7) * 8;                                                \
        size_t goff = (size_t)(m0 + row) * KD + (k0_) + col;                   \
        cp16((uint32_t)__cvta_generic_to_shared(&_ah[row][col]), g_w2h + goff);\
        cp16((uint32_t)__cvta_generic_to_shared(&_al[row][col]), g_w2l + goff);\
    }                                                                          \
    CP_COMMIT();                                                               \
} while (0)

    // ---- prologue: stage chunk 0 (stage 0), gather chunk 1 into regs ----
    BILIN(0);
    GATHER(0);
    STORE_B(0);
    STAGE_W(0, 0);
    GATHER(64);           // chunk 1 (tap 0, c0=64)
    int tap_cur = 0;

    for (int ch = 0; ch < 36; ++ch) {
        const int s = ch & 1;
        __syncthreads();   // MMA of ch-1 done -> stage s^1 free

        if (ch + 1 < 36) {
            const int nch = ch + 1;
            STORE_B(s ^ 1);                                    // v holds ch+1
            STAGE_W(s ^ 1, (nch >> 2) * 256 + (nch & 3) * 64);
            CP_WAIT1();    // completes stage s weights (committed last iter)
        } else {
            CP_WAIT0();
        }
        __syncthreads();   // As[s]/Bs[s] visible to all warps

        // gather ch+2 into regs; LDGs overlap the MMA below
        if (ch + 2 < 36) {
            int nntap = (ch + 2) >> 2;
            if (nntap != tap_cur) {
                BILIN(nntap);
                tap_cur = nntap;
            }
            GATHER(((ch + 2) & 3) * 64);
        }

        // MMA on stage s
        tile_t ash = AS_H(s), asl = AS_L(s), bsh = BS_H(s), bsl = BS_L(s);
#pragma unroll
        for (int ks = 0; ks < 64; ks += 16) {
            uint32_t bh[4][2], bl[4][2];
#pragma unroll
            for (int nf = 0; nf < 4; ++nf) {
                int nb = wn * 32 + nf * 8;
                ldsm_x2(bh[nf], b_addr(bsh, nb, ks, lid));
                ldsm_x2(bl[nf], b_addr(bsl, nb, ks, lid));
            }
#pragma unroll
            for (int mf = 0; mf < 2; ++mf) {
                int mb = wm * 32 + mf * 16;
                uint32_t ah[4], al[4];
                ldsm_x4(ah, a_addr(ash, mb, ks, lid));
                ldsm_x4(al, a_addr(asl, mb, ks, lid));
#pragma unroll
                for (int nf = 0; nf < 4; ++nf) {
                    mma16816(acc[mf][nf], ah, bh[nf]);
                    mma16816(acc[mf][nf], ah, bl[nf]);
                    mma16816(acc[mf][nf], al, bh[nf]);
                }
            }
        }
    }

    // epilogue: bias + relu -> g_r2
#pragma unroll
    for (int mf = 0; mf < 2; ++mf) {
#pragma unroll
        for (int half = 0; half < 2; ++half) {
            int o = m0 + wm * 32 + mf * 16 + q + half * 8;
            float bb = b2[o];
            float* orow = g_r2 + ((size_t)n * CB + o) * HW + pb;
#pragma unroll
            for (int nf = 0; nf < 4; ++nf) {
                int px = wn * 32 + nf * 8 + 2 * r;
                float2 ov;
                ov.x = fmaxf(acc[mf][nf][half * 2 + 0] + bb, 0.f);
                ov.y = fmaxf(acc[mf][nf][half * 2 + 1] + bb, 0.f);
                *(float2*)(orow + px) = ov;
            }
        }
    }
}

// ---------------------------------------------------------------------------
extern "C" void kernel_launch(void* const* d_in, const int* in_sizes, int n_in,
                              void* d_out, int out_size) {
    const float* x     = (const float*)d_in[0];
    const float* w1    = (const float*)d_in[1];
    const float* b1    = (const float*)d_in[2];
    const float* w_off = (const float*)d_in[3];
    const float* b_off = (const float*)d_in[4];
    const float* w2    = (const float*)d_in[5];
    const float* b2    = (const float*)d_in[6];
    const float* w3    = (const float*)d_in[7];
    const float* b3    = (const float*)d_in[8];
    float* out = (float*)d_out;

    float *r_ptr, *r2_ptr;
    cudaGetSymbolAddress((void**)&r_ptr, g_r);
    cudaGetSymbolAddress((void**)&r2_ptr, g_r2);

    cudaFuncSetAttribute(deform_mma_kernel,
                         cudaFuncAttributeMaxDynamicSharedMemorySize, DSM_BYTES);

    // w2 -> bf16 hi/lo, k = tap*256+c
    prep_w2_kernel<<<(CB * KD + 255) / 256, 256>>>(w2);

    // conv1: 1024 -> 256, relu (HMMA split-bf16)
    gemm_tc_kernel<<<dim3(HW / 64, CB / 128, Nn), 256>>>(
        w1, x, b1, nullptr, r_ptr, CB, CIN);

    // offset conv 3x3: 256 -> 18
    offset_conv_kernel<<<dim3(HW / 64, Nn), 256>>>(w_off, b_off);

    // deformable conv 3x3: 256 -> 256, relu (double-buffered HMMA)
    deform_mma_kernel<<<dim3(HW / 64, 2, Nn), 256, DSM_BYTES>>>(b2);

    // conv3: 256 -> 1024 + x residual, relu (HMMA split-bf16)
    gemm_tc_kernel<<<dim3(HW / 64, CIN / 128, Nn), 256>>>(
        w3, r2_ptr, b3, x, out, CIN, CB);
}